// round 15
// baseline (speedup 1.0000x reference)
#include <cuda_runtime.h>

#define NS 128    // sources (== threads per block)
#define NP 2048   // points per mirror
#define NM 64     // mirrors
#define NPTS (NM*NP)
#define NCYL 16
#define NBOX 8
#define IH 512
#define IW 512
#define NPIX (IH*IW)
#define NREP 4
#define PPB 4     // mirror points per render block
#define EXT 12.0f
#define EPSF 1e-9f
#define MARG 0.02f

// per-point scratch (written by prep_kernel, read by render_kernel)
__device__ float4 g_tp[NPTS];      // tpx, tpy, tpz, cull-mask (bits0-15 cyl, 16-23 box)
__device__ float4 g_tn[NPTS];      // tnx, tny, tnz, tnum
__device__ float4 g_cyl[NCYL];     // c1x, c1y, r^2, c1z
__device__ float  g_cylL[NCYL];    // axis length
__device__ float4 g_bx1[NBOX];     // box p1
__device__ float4 g_bx2[NBOX];     // box p2
__device__ float4 g_src[NS];       // sources, sorted y-major (x secondary)
// Privatized accumulation images. INVARIANT: zero at every kernel_launch
// entry — zero-initialized at module load, and reduce_kernel re-zeroes the
// words it consumes at the end of every launch.
__device__ float  g_img[NREP * NPIX];

__device__ __forceinline__ float sqrt_approx(float x) {
    float r; asm("sqrt.approx.f32 %0, %1;" : "=f"(r) : "f"(x)); return r;
}
__device__ __forceinline__ float rcp_approx(float x) {
    float r; asm("rcp.approx.f32 %0, %1;" : "=f"(r) : "f"(x)); return r;
}

// One thread per mirror point: transform + conservative cull + geometry tables.
// Block 0 additionally rank-sorts the sources (y-major) into g_src.
__global__ __launch_bounds__(128) void prep_kernel(
    const float* __restrict__ src,
    const float* __restrict__ mpoints,
    const float* __restrict__ mnormals,
    const float* __restrict__ mpos,
    const float* __restrict__ mrot,
    const float* __restrict__ cp1,
    const float* __restrict__ cp2,
    const float* __restrict__ crad,
    const float* __restrict__ bp1,
    const float* __restrict__ bp2,
    const float* __restrict__ spos,
    const float* __restrict__ snorm)
{
    const int tid = threadIdx.x;
    const int pid = blockIdx.x * 128 + tid;

    __shared__ float4 s_buf[192];        // [0:96) points, [96:192) normals (float4-packed)
    __shared__ float  s_cyl5[NCYL][5];   // c1x, c1y, c1z, c2z, r
    __shared__ float  s_box6[NBOX][6];   // b1xyz, b2xyz
    __shared__ float  sh[4][6];

    // ---- staged coalesced loads: 128 points = 384 floats = 96 float4 per array ----
    {
        const float4* mp4 = (const float4*)mpoints  + blockIdx.x * 96;
        const float4* nv4 = (const float4*)mnormals + blockIdx.x * 96;
        if (tid < 96) {
            s_buf[tid]      = mp4[tid];
            s_buf[96 + tid] = nv4[tid];
        } else {
            int i = tid - 96;            // 0..31: stage obstacle tables
            if (i < NCYL) {
                s_cyl5[i][0] = cp1[3*i];
                s_cyl5[i][1] = cp1[3*i+1];
                s_cyl5[i][2] = cp1[3*i+2];
                s_cyl5[i][3] = cp2[3*i+2];
                s_cyl5[i][4] = crad[i];
            } else {
                int b = i - NCYL;
                s_box6[b][0] = bp1[3*b];
                s_box6[b][1] = bp1[3*b+1];
                s_box6[b][2] = bp1[3*b+2];
                s_box6[b][3] = bp2[3*b];
                s_box6[b][4] = bp2[3*b+1];
                s_box6[b][5] = bp2[3*b+2];
            }
        }
    }

    // geometry tables for render (block 0 only)
    if (blockIdx.x == 0) {
        if (tid < NCYL) {
            float r = crad[tid];
            g_cyl[tid]  = make_float4(cp1[3*tid], cp1[3*tid+1], r * r, cp1[3*tid+2]);
            g_cylL[tid] = fabsf(cp2[3*tid+2] - cp1[3*tid+2]);
        } else if (tid < NCYL + NBOX) {
            int b = tid - NCYL;
            g_bx1[b] = make_float4(bp1[3*b], bp1[3*b+1], bp1[3*b+2], 0.f);
            g_bx2[b] = make_float4(bp2[3*b], bp2[3*b+1], bp2[3*b+2], 0.f);
        }
    }

    // ---- uniform per-block loads (one mirror per block) ----
    const int m = blockIdx.x >> 4;       // 16 blocks per mirror
    const float* R = mrot + m * 9;
    float r00 = R[0], r01 = R[1], r02 = R[2];
    float r10 = R[3], r11 = R[4], r12 = R[5];
    float r20 = R[6], r21 = R[7], r22 = R[8];
    float mp0 = mpos[m*3+0], mp1 = mpos[m*3+1], mp2 = mpos[m*3+2];

    // ---- block-local source-bounds reduction (128 sources, one per thread) ----
    float x = src[tid*3], y = src[tid*3+1], z = src[tid*3+2];
    float xmn = x, xmx = x, ymn = y, ymx = y, zmn = z, zmx = z;
    #pragma unroll
    for (int o = 16; o; o >>= 1) {
        xmn = fminf(xmn, __shfl_xor_sync(0xffffffffu, xmn, o));
        xmx = fmaxf(xmx, __shfl_xor_sync(0xffffffffu, xmx, o));
        ymn = fminf(ymn, __shfl_xor_sync(0xffffffffu, ymn, o));
        ymx = fmaxf(ymx, __shfl_xor_sync(0xffffffffu, ymx, o));
        zmn = fminf(zmn, __shfl_xor_sync(0xffffffffu, zmn, o));
        zmx = fmaxf(zmx, __shfl_xor_sync(0xffffffffu, zmx, o));
    }
    int w = tid >> 5;
    if ((tid & 31) == 0) {
        sh[w][0] = xmn; sh[w][1] = xmx; sh[w][2] = ymn;
        sh[w][3] = ymx; sh[w][4] = zmn; sh[w][5] = zmx;
    }
    __syncthreads();   // covers sh, s_buf, s_cyl5, s_box6
    xmn = fminf(fminf(sh[0][0], sh[1][0]), fminf(sh[2][0], sh[3][0]));
    xmx = fmaxf(fmaxf(sh[0][1], sh[1][1]), fmaxf(sh[2][1], sh[3][1]));
    ymn = fminf(fminf(sh[0][2], sh[1][2]), fminf(sh[2][2], sh[3][2]));
    ymx = fmaxf(fmaxf(sh[0][3], sh[1][3]), fmaxf(sh[2][3], sh[3][3]));
    zmn = fminf(fminf(sh[0][4], sh[1][4]), fminf(sh[2][4], sh[3][4]));
    zmx = fmaxf(fmaxf(sh[0][5], sh[1][5]), fmaxf(sh[2][5], sh[3][5]));

    // ---- per-point transform (point/normal from shared) ----
    const float* sp = (const float*)s_buf;
    float px = sp[3*tid],       py = sp[3*tid+1],       pz = sp[3*tid+2];
    float vx = sp[384 + 3*tid], vy = sp[384 + 3*tid+1], vz = sp[384 + 3*tid+2];
    float tpx = fmaf(r00, px, fmaf(r01, py, r02 * pz)) + mp0;
    float tpy = fmaf(r10, px, fmaf(r11, py, r12 * pz)) + mp1;
    float tpz = fmaf(r20, px, fmaf(r21, py, r22 * pz)) + mp2;
    float tnx = fmaf(r00, vx, fmaf(r01, vy, r02 * vz));
    float tny = fmaf(r10, vx, fmaf(r11, vy, r12 * vz));
    float tnz = fmaf(r20, vx, fmaf(r21, vy, r22 * vz));

    float Nx = snorm[0], Ny = snorm[1], Nz = snorm[2];
    float tnum = fmaf(spos[0] - tpx, Nx,
                 fmaf(spos[1] - tpy, Ny, (spos[2] - tpz) * Nz));

    // ---- conservative occlusion cull (obstacles from shared) ----
    unsigned mask;
    float dzl = zmn - tpz, dzh = zmx - tpz;
    if (dzl <= 0.01f) {
        mask = (0xFFu << 16) | 0xFFFFu;   // sources not clearly above: keep all
    } else {
        float rdl = __fdividef(1.0f, dzl), rdh = __fdividef(1.0f, dzh);
        float nxl = xmn - tpx, nxh = xmx - tpx;
        float nyl = ymn - tpy, nyh = ymx - tpy;
        float wxl = fminf(fminf(nxl*rdl, nxl*rdh) - 1e-4f, 0.f);
        float wxh = fmaxf(fmaxf(nxh*rdl, nxh*rdh) + 1e-4f, 0.f);
        float wyl = fminf(fminf(nyl*rdl, nyl*rdh) - 1e-4f, 0.f);
        float wyh = fmaxf(fmaxf(nyh*rdl, nyh*rdh) + 1e-4f, 0.f);
        mask = 0u;
        #pragma unroll
        for (int c = 0; c < NCYL; c++) {
            float c1x = s_cyl5[c][0], c1y = s_cyl5[c][1], c1z = s_cyl5[c][2];
            float c2z = s_cyl5[c][3];
            float r   = s_cyl5[c][4];
            float dmax = fmaxf(c1z, c2z) - tpz + MARG;
            float Xl = fmaf(dmax, wxl, tpx), Xh = fmaf(dmax, wxh, tpx);
            float Yl = fmaf(dmax, wyl, tpy), Yh = fmaf(dmax, wyh, tpy);
            float ddx = fmaxf(fmaxf(c1x - Xh, Xl - c1x), 0.f);
            float ddy = fmaxf(fmaxf(c1y - Yh, Yl - c1y), 0.f);
            float rr = r + MARG;
            if ((dmax > 0.f) & (fmaf(ddx, ddx, ddy*ddy) <= rr*rr)) mask |= (1u << c);
        }
        #pragma unroll
        for (int b = 0; b < NBOX; b++) {
            float b1x = s_box6[b][0], b1y = s_box6[b][1];
            float b2x = s_box6[b][3], b2y = s_box6[b][4], b2z = s_box6[b][5];
            float d2 = b2z - tpz + MARG;
            float Xl = fmaf(d2, wxl, tpx), Xh = fmaf(d2, wxh, tpx);
            float Yl = fmaf(d2, wyl, tpy), Yh = fmaf(d2, wyh, tpy);
            bool act = (d2 > 0.f) & (Xh >= b1x - MARG) & (Xl <= b2x + MARG)
                                  & (Yh >= b1y - MARG) & (Yl <= b2y + MARG);
            if (act) mask |= (1u << (16 + b));
        }
    }

    g_tp[pid] = make_float4(tpx, tpy, tpz, __uint_as_float(mask));
    g_tn[pid] = make_float4(tnx, tny, tnz, tnum);

    // ---- block 0: rank-sort sources y-major (x secondary) so that warp
    // lanes (32 consecutive sorted sources) land on few pixel rows ----
    if (blockIdx.x == 0) {
        __shared__ float sy_[NS], sx_[NS];
        sy_[tid] = y; sx_[tid] = x;
        __syncthreads();
        int rank = 0;
        #pragma unroll 8
        for (int i = 0; i < NS; i++) {
            float yi = sy_[i], xi = sx_[i];
            bool less = (yi < y) | ((yi == y) & ((xi < x) | ((xi == x) & (i < tid))));
            rank += (int)less;
        }
        g_src[rank] = make_float4(x, y, z, 0.f);
    }
}

// Sum the replicas into the output image AND restore the replicas to zero
// (maintains the g_img==0 entry invariant for the next launch/replay).
__global__ __launch_bounds__(256) void reduce_kernel(float4* __restrict__ out4) {
    int base = blockIdx.x * 512 + threadIdx.x;
    float4* img4 = (float4*)g_img;
    const float4 z4 = make_float4(0.f, 0.f, 0.f, 0.f);
    #pragma unroll
    for (int k = 0; k < 2; k++) {
        int i = base + k * 256;   // 0 .. NPIX/4-1
        float4 a = img4[i];
        img4[i] = z4;
        #pragma unroll
        for (int r = 1; r < NREP; r++) {
            float4 b = img4[r * (NPIX/4) + i];
            img4[r * (NPIX/4) + i] = z4;
            a.x += b.x; a.y += b.y; a.z += b.z; a.w += b.w;
        }
        out4[i] = a;
    }
}

__global__ __launch_bounds__(NS) void render_kernel(
    const float* __restrict__ snorm)
{
    const int tid = threadIdx.x;
    const int pid0 = blockIdx.x * PPB;

    float4 s4 = g_src[tid];
    float sx = s4.x, sy = s4.y, sz = s4.z;
    const float Nx = snorm[0], Ny = snorm[1], Nz = snorm[2];

    // warp-uniform replica: lanes of one warp share an image so sorted
    // sources translate into shared 128B lines at the atomic; the block's
    // 4 warps cover all 4 replicas.
    float* img = g_img + ((blockIdx.x + (tid >> 5)) & (NREP - 1)) * NPIX;

    // batch-load all point records up front
    float4 tp[PPB], tn[PPB];
    #pragma unroll
    for (int j = 0; j < PPB; j++) {
        tp[j] = g_tp[pid0 + j];
        tn[j] = g_tn[pid0 + j];
    }

    #pragma unroll
    for (int jj = 0; jj < PPB; jj++) {
        float4 tp4 = tp[jj];
        float4 tn4 = tn[jj];
        unsigned mask = __float_as_uint(tp4.w);
        unsigned cm = mask & 0xFFFFu;
        unsigned bm = mask >> 16;
        float tpx = tp4.x, tpy = tp4.y, tpz = tp4.z;

        // unnormalized occlusion direction (mirror point -> source)
        float ux = sx - tpx, uy = sy - tpy, uz = sz - tpz;
        float A = fmaf(ux, ux, uy * uy);     // |u_perp|^2 (vertical axes)

        bool blocked = false;
        while (cm) {
            int c = __ffs(cm) - 1; cm &= cm - 1;
            float4 cg = g_cyl[c];
            float mx = tpx - cg.x, my = tpy - cg.y;
            float hB = fmaf(ux, mx, uy * my);
            float C  = fmaf(mx, mx, fmaf(my, my, -cg.z));
            float dp = fmaf(hB, hB, -A * C);
            if (dp > 0.0f) {
                float L  = g_cylL[c];
                float oa = tpz - cg.w;
                float sq  = sqrt_approx(dp);
                float inv = __fdividef(1.0f, fmaf(2.0f, A, EPSF));
                float t1  = (-2.0f * hB - 2.0f * sq) * inv;
                float t2  = (-2.0f * hB + 2.0f * sq) * inv;
                float x1  = fmaf(t1, uz, oa);
                float x2  = fmaf(t2, uz, oa);
                bool h1 = (t1 > EPSF) & (x1 >= 0.0f) & (x1 <= L);
                bool h2 = (t2 > EPSF) & (x2 >= 0.0f) & (x2 <= L);
                blocked |= (h1 | h2);
            }
        }

        if (bm && !blocked) {
            float aux = (fabsf(ux) < EPSF) ? EPSF : ux;
            float auy = (fabsf(uy) < EPSF) ? EPSF : uy;
            float auz = (fabsf(uz) < EPSF) ? EPSF : uz;
            float ivx = __fdividef(1.0f, aux);
            float ivy = __fdividef(1.0f, auy);
            float ivz = __fdividef(1.0f, auz);
            while (bm) {
                int b = __ffs(bm) - 1; bm &= bm - 1;
                float4 v1 = g_bx1[b];
                float4 v2 = g_bx2[b];
                float lx = (v1.x - tpx) * ivx, hx = (v2.x - tpx) * ivx;
                float ly = (v1.y - tpy) * ivy, hy = (v2.y - tpy) * ivy;
                float lz = (v1.z - tpz) * ivz, hz = (v2.z - tpz) * ivz;
                float nx_ = fminf(lx, hx), xx_ = fmaxf(lx, hx);
                float ny_ = fminf(ly, hy), xy_ = fmaxf(ly, hy);
                float nz_ = fminf(lz, hz), xz_ = fmaxf(lz, hz);
                float tmin = fmaxf(fmaxf(nx_, ny_), nz_);
                float tmax = fminf(fminf(xx_, xy_), xz_);
                blocked |= (tmax >= fmaxf(tmin, EPSF));
            }
        }

        if (!blocked) {
            float un  = fmaf(ux, tn4.x, fmaf(uy, tn4.y, uz * tn4.z));
            float r0x = fmaf(2.0f * un, tn4.x, -ux);
            float r0y = fmaf(2.0f * un, tn4.y, -uy);
            float r0z = fmaf(2.0f * un, tn4.z, -uz);
            float denom = fmaf(r0x, Nx, fmaf(r0y, Ny, r0z * Nz)) + EPSF;
            float t  = tn4.w * rcp_approx(denom);
            float qx = fmaf(t, r0x, tpx);
            float qy = fmaf(t, r0y, tpy);
            float len2 = fmaf(uz, uz, A);
            float il   = rsqrtf(len2);
            float cosv = fabsf(un) * il;
            const float K = (float)IW / (2.0f * EXT);
            float fx = fmaf(qx, K, 0.5f * (float)IW);
            float fy = fmaf(qy, K, 0.5f * (float)IH);
            float flx = floorf(fx), fly = floorf(fy);
            if (flx >= 0.0f && flx < (float)IW && fly >= 0.0f && fly < (float)IH) {
                int ix = (int)flx;
                int iy = (int)fly;
                atomicAdd(img + iy * IW + ix, cosv);
            }
        }
    }
}

extern "C" void kernel_launch(void* const* d_in, const int* in_sizes, int n_in,
                              void* d_out, int out_size) {
    float* out = (float*)d_out;
    prep_kernel<<<NPTS / 128, 128>>>(
        (const float*)d_in[0],   // sources
        (const float*)d_in[1],   // mirror_points
        (const float*)d_in[2],   // mirror_normals
        (const float*)d_in[3],   // mirror_positions
        (const float*)d_in[4],   // mirror_rotations
        (const float*)d_in[5],   // cyl_p1
        (const float*)d_in[6],   // cyl_p2
        (const float*)d_in[7],   // cyl_radius
        (const float*)d_in[8],   // box_p1
        (const float*)d_in[9],   // box_p2
        (const float*)d_in[10],  // sensor_plane_pos
        (const float*)d_in[11]); // sensor_plane_normal
    render_kernel<<<NPTS / PPB, NS>>>(
        (const float*)d_in[11]); // sensor_plane_normal
    reduce_kernel<<<NPIX / 4 / 512, 256>>>((float4*)out);
}

// round 16
// speedup vs baseline: 1.0987x; 1.0987x over previous
#include <cuda_runtime.h>

#define NS 128    // sources (== threads per block)
#define NP 2048   // points per mirror
#define NM 64     // mirrors
#define NPTS (NM*NP)
#define NCYL 16
#define NBOX 8
#define IH 512
#define IW 512
#define NPIX (IH*IW)
#define NREP 8
#define PPB 4     // mirror points per render block
#define EXT 12.0f
#define EPSF 1e-9f
#define MARG 0.02f

// per-point scratch (written by prep_kernel, read by render_kernel)
__device__ float4 g_tp[NPTS];      // tpx, tpy, tpz, cull-mask (bits0-15 cyl, 16-23 box)
__device__ float4 g_tn[NPTS];      // tnx, tny, tnz, tnum
__device__ float4 g_cyl[NCYL];     // c1x, c1y, r^2, c1z
__device__ float  g_cylL[NCYL];    // axis length
__device__ float4 g_bx1[NBOX];     // box p1
__device__ float4 g_bx2[NBOX];     // box p2
__device__ float4 g_src[NS];       // sources, sorted y-major (x secondary)
// Privatized accumulation images. INVARIANT: zero at every kernel_launch
// entry — zero-initialized at module load, and reduce_kernel re-zeroes the
// words it consumes at the end of every launch.
__device__ float  g_img[NREP * NPIX];

__device__ __forceinline__ float sqrt_approx(float x) {
    float r; asm("sqrt.approx.f32 %0, %1;" : "=f"(r) : "f"(x)); return r;
}
__device__ __forceinline__ float rcp_approx(float x) {
    float r; asm("rcp.approx.f32 %0, %1;" : "=f"(r) : "f"(x)); return r;
}

// One thread per mirror point: transform + conservative cull + geometry tables.
// Block 0 additionally rank-sorts the sources (y-major) into g_src.
__global__ __launch_bounds__(128) void prep_kernel(
    const float* __restrict__ src,
    const float* __restrict__ mpoints,
    const float* __restrict__ mnormals,
    const float* __restrict__ mpos,
    const float* __restrict__ mrot,
    const float* __restrict__ cp1,
    const float* __restrict__ cp2,
    const float* __restrict__ crad,
    const float* __restrict__ bp1,
    const float* __restrict__ bp2,
    const float* __restrict__ spos,
    const float* __restrict__ snorm)
{
    const int tid = threadIdx.x;
    const int pid = blockIdx.x * 128 + tid;

    __shared__ float4 s_buf[192];        // [0:96) points, [96:192) normals (float4-packed)
    __shared__ float  s_cyl5[NCYL][5];   // c1x, c1y, c1z, c2z, r
    __shared__ float  s_box6[NBOX][6];   // b1xyz, b2xyz
    __shared__ float  sh[4][6];

    // ---- staged coalesced loads: 128 points = 384 floats = 96 float4 per array ----
    {
        const float4* mp4 = (const float4*)mpoints  + blockIdx.x * 96;
        const float4* nv4 = (const float4*)mnormals + blockIdx.x * 96;
        if (tid < 96) {
            s_buf[tid]      = mp4[tid];
            s_buf[96 + tid] = nv4[tid];
        } else {
            int i = tid - 96;            // 0..31: stage obstacle tables
            if (i < NCYL) {
                s_cyl5[i][0] = cp1[3*i];
                s_cyl5[i][1] = cp1[3*i+1];
                s_cyl5[i][2] = cp1[3*i+2];
                s_cyl5[i][3] = cp2[3*i+2];
                s_cyl5[i][4] = crad[i];
            } else {
                int b = i - NCYL;
                s_box6[b][0] = bp1[3*b];
                s_box6[b][1] = bp1[3*b+1];
                s_box6[b][2] = bp1[3*b+2];
                s_box6[b][3] = bp2[3*b];
                s_box6[b][4] = bp2[3*b+1];
                s_box6[b][5] = bp2[3*b+2];
            }
        }
    }

    // geometry tables for render (block 0 only)
    if (blockIdx.x == 0) {
        if (tid < NCYL) {
            float r = crad[tid];
            g_cyl[tid]  = make_float4(cp1[3*tid], cp1[3*tid+1], r * r, cp1[3*tid+2]);
            g_cylL[tid] = fabsf(cp2[3*tid+2] - cp1[3*tid+2]);
        } else if (tid < NCYL + NBOX) {
            int b = tid - NCYL;
            g_bx1[b] = make_float4(bp1[3*b], bp1[3*b+1], bp1[3*b+2], 0.f);
            g_bx2[b] = make_float4(bp2[3*b], bp2[3*b+1], bp2[3*b+2], 0.f);
        }
    }

    // ---- uniform per-block loads (one mirror per block) ----
    const int m = blockIdx.x >> 4;       // 16 blocks per mirror
    const float* R = mrot + m * 9;
    float r00 = R[0], r01 = R[1], r02 = R[2];
    float r10 = R[3], r11 = R[4], r12 = R[5];
    float r20 = R[6], r21 = R[7], r22 = R[8];
    float mp0 = mpos[m*3+0], mp1 = mpos[m*3+1], mp2 = mpos[m*3+2];

    // ---- block-local source-bounds reduction (128 sources, one per thread) ----
    float x = src[tid*3], y = src[tid*3+1], z = src[tid*3+2];
    float xmn = x, xmx = x, ymn = y, ymx = y, zmn = z, zmx = z;
    #pragma unroll
    for (int o = 16; o; o >>= 1) {
        xmn = fminf(xmn, __shfl_xor_sync(0xffffffffu, xmn, o));
        xmx = fmaxf(xmx, __shfl_xor_sync(0xffffffffu, xmx, o));
        ymn = fminf(ymn, __shfl_xor_sync(0xffffffffu, ymn, o));
        ymx = fmaxf(ymx, __shfl_xor_sync(0xffffffffu, ymx, o));
        zmn = fminf(zmn, __shfl_xor_sync(0xffffffffu, zmn, o));
        zmx = fmaxf(zmx, __shfl_xor_sync(0xffffffffu, zmx, o));
    }
    int w = tid >> 5;
    if ((tid & 31) == 0) {
        sh[w][0] = xmn; sh[w][1] = xmx; sh[w][2] = ymn;
        sh[w][3] = ymx; sh[w][4] = zmn; sh[w][5] = zmx;
    }
    __syncthreads();   // covers sh, s_buf, s_cyl5, s_box6
    xmn = fminf(fminf(sh[0][0], sh[1][0]), fminf(sh[2][0], sh[3][0]));
    xmx = fmaxf(fmaxf(sh[0][1], sh[1][1]), fmaxf(sh[2][1], sh[3][1]));
    ymn = fminf(fminf(sh[0][2], sh[1][2]), fminf(sh[2][2], sh[3][2]));
    ymx = fmaxf(fmaxf(sh[0][3], sh[1][3]), fmaxf(sh[2][3], sh[3][3]));
    zmn = fminf(fminf(sh[0][4], sh[1][4]), fminf(sh[2][4], sh[3][4]));
    zmx = fmaxf(fmaxf(sh[0][5], sh[1][5]), fmaxf(sh[2][5], sh[3][5]));

    // ---- per-point transform (point/normal from shared) ----
    const float* sp = (const float*)s_buf;
    float px = sp[3*tid],       py = sp[3*tid+1],       pz = sp[3*tid+2];
    float vx = sp[384 + 3*tid], vy = sp[384 + 3*tid+1], vz = sp[384 + 3*tid+2];
    float tpx = fmaf(r00, px, fmaf(r01, py, r02 * pz)) + mp0;
    float tpy = fmaf(r10, px, fmaf(r11, py, r12 * pz)) + mp1;
    float tpz = fmaf(r20, px, fmaf(r21, py, r22 * pz)) + mp2;
    float tnx = fmaf(r00, vx, fmaf(r01, vy, r02 * vz));
    float tny = fmaf(r10, vx, fmaf(r11, vy, r12 * vz));
    float tnz = fmaf(r20, vx, fmaf(r21, vy, r22 * vz));

    float Nx = snorm[0], Ny = snorm[1], Nz = snorm[2];
    float tnum = fmaf(spos[0] - tpx, Nx,
                 fmaf(spos[1] - tpy, Ny, (spos[2] - tpz) * Nz));

    // ---- conservative occlusion cull (obstacles from shared) ----
    unsigned mask;
    float dzl = zmn - tpz, dzh = zmx - tpz;
    if (dzl <= 0.01f) {
        mask = (0xFFu << 16) | 0xFFFFu;   // sources not clearly above: keep all
    } else {
        float rdl = __fdividef(1.0f, dzl), rdh = __fdividef(1.0f, dzh);
        float nxl = xmn - tpx, nxh = xmx - tpx;
        float nyl = ymn - tpy, nyh = ymx - tpy;
        float wxl = fminf(fminf(nxl*rdl, nxl*rdh) - 1e-4f, 0.f);
        float wxh = fmaxf(fmaxf(nxh*rdl, nxh*rdh) + 1e-4f, 0.f);
        float wyl = fminf(fminf(nyl*rdl, nyl*rdh) - 1e-4f, 0.f);
        float wyh = fmaxf(fmaxf(nyh*rdl, nyh*rdh) + 1e-4f, 0.f);
        mask = 0u;
        #pragma unroll
        for (int c = 0; c < NCYL; c++) {
            float c1x = s_cyl5[c][0], c1y = s_cyl5[c][1], c1z = s_cyl5[c][2];
            float c2z = s_cyl5[c][3];
            float r   = s_cyl5[c][4];
            float dmax = fmaxf(c1z, c2z) - tpz + MARG;
            float Xl = fmaf(dmax, wxl, tpx), Xh = fmaf(dmax, wxh, tpx);
            float Yl = fmaf(dmax, wyl, tpy), Yh = fmaf(dmax, wyh, tpy);
            float ddx = fmaxf(fmaxf(c1x - Xh, Xl - c1x), 0.f);
            float ddy = fmaxf(fmaxf(c1y - Yh, Yl - c1y), 0.f);
            float rr = r + MARG;
            if ((dmax > 0.f) & (fmaf(ddx, ddx, ddy*ddy) <= rr*rr)) mask |= (1u << c);
        }
        #pragma unroll
        for (int b = 0; b < NBOX; b++) {
            float b1x = s_box6[b][0], b1y = s_box6[b][1];
            float b2x = s_box6[b][3], b2y = s_box6[b][4], b2z = s_box6[b][5];
            float d2 = b2z - tpz + MARG;
            float Xl = fmaf(d2, wxl, tpx), Xh = fmaf(d2, wxh, tpx);
            float Yl = fmaf(d2, wyl, tpy), Yh = fmaf(d2, wyh, tpy);
            bool act = (d2 > 0.f) & (Xh >= b1x - MARG) & (Xl <= b2x + MARG)
                                  & (Yh >= b1y - MARG) & (Yl <= b2y + MARG);
            if (act) mask |= (1u << (16 + b));
        }
    }

    g_tp[pid] = make_float4(tpx, tpy, tpz, __uint_as_float(mask));
    g_tn[pid] = make_float4(tnx, tny, tnz, tnum);

    // ---- block 0: rank-sort sources y-major (x secondary) so that warp
    // lanes (32 consecutive sorted sources) land on few pixel rows ----
    if (blockIdx.x == 0) {
        __shared__ float sy_[NS], sx_[NS];
        sy_[tid] = y; sx_[tid] = x;
        __syncthreads();
        int rank = 0;
        #pragma unroll 8
        for (int i = 0; i < NS; i++) {
            float yi = sy_[i], xi = sx_[i];
            bool less = (yi < y) | ((yi == y) & ((xi < x) | ((xi == x) & (i < tid))));
            rank += (int)less;
        }
        g_src[rank] = make_float4(x, y, z, 0.f);
    }
}

// Sum the replicas into the output image AND restore the replicas to zero
// (maintains the g_img==0 entry invariant for the next launch/replay).
// 256 blocks x 256 threads: one float4 chunk per thread, full-chip spread.
__global__ __launch_bounds__(256) void reduce_kernel(float4* __restrict__ out4) {
    int i = blockIdx.x * 256 + threadIdx.x;   // 0 .. NPIX/4-1
    float4* img4 = (float4*)g_img;
    const float4 z4 = make_float4(0.f, 0.f, 0.f, 0.f);
    float4 a = img4[i];
    img4[i] = z4;
    #pragma unroll
    for (int r = 1; r < NREP; r++) {
        float4 b = img4[r * (NPIX/4) + i];
        img4[r * (NPIX/4) + i] = z4;
        a.x += b.x; a.y += b.y; a.z += b.z; a.w += b.w;
    }
    out4[i] = a;
}

__global__ __launch_bounds__(NS) void render_kernel(
    const float* __restrict__ snorm)
{
    const int tid = threadIdx.x;
    const int pid0 = blockIdx.x * PPB;

    float4 s4 = g_src[tid];
    float sx = s4.x, sy = s4.y, sz = s4.z;
    const float Nx = snorm[0], Ny = snorm[1], Nz = snorm[2];

    // warp-uniform replica: lanes of one warp share an image so sorted
    // sources translate into shared 128B lines at the atomic.
    float* img = g_img + ((blockIdx.x + ((tid >> 5) << 1)) & (NREP - 1)) * NPIX;

    // batch-load all point records up front
    float4 tp[PPB], tn[PPB];
    #pragma unroll
    for (int j = 0; j < PPB; j++) {
        tp[j] = g_tp[pid0 + j];
        tn[j] = g_tn[pid0 + j];
    }

    #pragma unroll
    for (int jj = 0; jj < PPB; jj++) {
        float4 tp4 = tp[jj];
        float4 tn4 = tn[jj];
        unsigned mask = __float_as_uint(tp4.w);
        unsigned cm = mask & 0xFFFFu;
        unsigned bm = mask >> 16;
        float tpx = tp4.x, tpy = tp4.y, tpz = tp4.z;

        // unnormalized occlusion direction (mirror point -> source)
        float ux = sx - tpx, uy = sy - tpy, uz = sz - tpz;
        float A = fmaf(ux, ux, uy * uy);     // |u_perp|^2 (vertical axes)

        bool blocked = false;
        while (cm) {
            int c = __ffs(cm) - 1; cm &= cm - 1;
            float4 cg = g_cyl[c];
            float mx = tpx - cg.x, my = tpy - cg.y;
            float hB = fmaf(ux, mx, uy * my);
            float C  = fmaf(mx, mx, fmaf(my, my, -cg.z));
            float dp = fmaf(hB, hB, -A * C);
            if (dp > 0.0f) {
                float L  = g_cylL[c];
                float oa = tpz - cg.w;
                float sq  = sqrt_approx(dp);
                float inv = __fdividef(1.0f, fmaf(2.0f, A, EPSF));
                float t1  = (-2.0f * hB - 2.0f * sq) * inv;
                float t2  = (-2.0f * hB + 2.0f * sq) * inv;
                float x1  = fmaf(t1, uz, oa);
                float x2  = fmaf(t2, uz, oa);
                bool h1 = (t1 > EPSF) & (x1 >= 0.0f) & (x1 <= L);
                bool h2 = (t2 > EPSF) & (x2 >= 0.0f) & (x2 <= L);
                blocked |= (h1 | h2);
            }
        }

        if (bm && !blocked) {
            float aux = (fabsf(ux) < EPSF) ? EPSF : ux;
            float auy = (fabsf(uy) < EPSF) ? EPSF : uy;
            float auz = (fabsf(uz) < EPSF) ? EPSF : uz;
            float ivx = __fdividef(1.0f, aux);
            float ivy = __fdividef(1.0f, auy);
            float ivz = __fdividef(1.0f, auz);
            while (bm) {
                int b = __ffs(bm) - 1; bm &= bm - 1;
                float4 v1 = g_bx1[b];
                float4 v2 = g_bx2[b];
                float lx = (v1.x - tpx) * ivx, hx = (v2.x - tpx) * ivx;
                float ly = (v1.y - tpy) * ivy, hy = (v2.y - tpy) * ivy;
                float lz = (v1.z - tpz) * ivz, hz = (v2.z - tpz) * ivz;
                float nx_ = fminf(lx, hx), xx_ = fmaxf(lx, hx);
                float ny_ = fminf(ly, hy), xy_ = fmaxf(ly, hy);
                float nz_ = fminf(lz, hz), xz_ = fmaxf(lz, hz);
                float tmin = fmaxf(fmaxf(nx_, ny_), nz_);
                float tmax = fminf(fminf(xx_, xy_), xz_);
                blocked |= (tmax >= fmaxf(tmin, EPSF));
            }
        }

        if (!blocked) {
            float un  = fmaf(ux, tn4.x, fmaf(uy, tn4.y, uz * tn4.z));
            float r0x = fmaf(2.0f * un, tn4.x, -ux);
            float r0y = fmaf(2.0f * un, tn4.y, -uy);
            float r0z = fmaf(2.0f * un, tn4.z, -uz);
            float denom = fmaf(r0x, Nx, fmaf(r0y, Ny, r0z * Nz)) + EPSF;
            float t  = tn4.w * rcp_approx(denom);
            float qx = fmaf(t, r0x, tpx);
            float qy = fmaf(t, r0y, tpy);
            float len2 = fmaf(uz, uz, A);
            float il   = rsqrtf(len2);
            float cosv = fabsf(un) * il;
            const float K = (float)IW / (2.0f * EXT);
            float fx = fmaf(qx, K, 0.5f * (float)IW);
            float fy = fmaf(qy, K, 0.5f * (float)IH);
            float flx = floorf(fx), fly = floorf(fy);
            if (flx >= 0.0f && flx < (float)IW && fly >= 0.0f && fly < (float)IH) {
                int ix = (int)flx;
                int iy = (int)fly;
                atomicAdd(img + iy * IW + ix, cosv);
            }
        }
    }
}

extern "C" void kernel_launch(void* const* d_in, const int* in_sizes, int n_in,
                              void* d_out, int out_size) {
    float* out = (float*)d_out;
    prep_kernel<<<NPTS / 128, 128>>>(
        (const float*)d_in[0],   // sources
        (const float*)d_in[1],   // mirror_points
        (const float*)d_in[2],   // mirror_normals
        (const float*)d_in[3],   // mirror_positions
        (const float*)d_in[4],   // mirror_rotations
        (const float*)d_in[5],   // cyl_p1
        (const float*)d_in[6],   // cyl_p2
        (const float*)d_in[7],   // cyl_radius
        (const float*)d_in[8],   // box_p1
        (const float*)d_in[9],   // box_p2
        (const float*)d_in[10],  // sensor_plane_pos
        (const float*)d_in[11]); // sensor_plane_normal
    render_kernel<<<NPTS / PPB, NS>>>(
        (const float*)d_in[11]); // sensor_plane_normal
    reduce_kernel<<<NPIX / 4 / 256, 256>>>((float4*)out);
}